// round 6
// baseline (speedup 1.0000x reference)
#include <cuda_runtime.h>
#include <cstdint>

#define NF    33        // feature_dim + flag
#define BOND  64
#define NB    4         // batches per CTA
#define OUTD  32
#define TLEN  512
#define NTH   256
#define NPAIR (BOND * NF)   // 2112

__device__ __forceinline__ void cp_async4(uint32_t smem_addr, const void* gptr) {
    asm volatile("cp.async.ca.shared.global [%0], [%1], 4;\n"
                 :: "r"(smem_addr), "l"(gptr));
}
__device__ __forceinline__ void cp_async_commit() {
    asm volatile("cp.async.commit_group;\n" ::: "memory");
}
__device__ __forceinline__ void cp_async_wait0() {
    asm volatile("cp.async.wait_group 0;\n" ::: "memory");
}

__global__ __launch_bounds__(NTH, 1)
void umps_chain_kernel(const float* __restrict__ x,      // (256, 512, 33)
                       const float* __restrict__ core,   // (64, 33, 64)
                       const float* __restrict__ alpha,  // (64)
                       const float* __restrict__ outc,   // (64, 32)
                       float*       __restrict__ out)    // (256, 32)
{
    // sU: U[i][f][b] during compute; aliased as reduction partials afterwards
    // (phases separated by __syncthreads()).
    __shared__ float sU[NPAIR * 4];        // 33792 B
    __shared__ float sV[BOND * 4];         // V[i][b]   (i = bond index)
    __shared__ float sX[2][NF * 4];        // X[f][b], double-buffered over t

    const int tid = threadIdx.x;
    const int w   = tid >> 5;
    const int l   = tid & 31;
    const int il  = l >> 4;          // 0..1
    const int jv  = l & 15;          // 0..15  -> j = jv*4 .. jv*4+3
    const int g   = (w << 1) | il;   // 0..15  -> i-group
    const int b0  = blockIdx.x * NB; // global batch base

    // ---- init V[i][b] = alpha[i] ----
    if (tid < BOND) {
        float a = alpha[tid];
        sV[tid * 4 + 0] = a; sV[tid * 4 + 1] = a;
        sV[tid * 4 + 2] = a; sV[tid * 4 + 3] = a;
    }

    // ---- preload X(t=0) via cp.async ----
    const uint32_t xs_base = (uint32_t)__cvta_generic_to_shared(&sX[0][0]);
    if (tid < NF * NB) {
        int b = tid & 3, f = tid >> 2;
        const float* src = x + ((size_t)(b0 + b) * TLEN + 0) * NF + f;
        cp_async4(xs_base + (uint32_t)((f * 4 + b) * 4), src);
    }
    cp_async_commit();

    for (int t = 0; t < TLEN; ++t) {
        cp_async_wait0();
        __syncthreads();   // B0: X(t), V(t) ready; sU free for rebuild

        // ---- build U[i][f][b] = V[i][b] * X[f][b] ----
        const int buf = t & 1;
        for (int p = tid; p < NPAIR; p += NTH) {
            int i = p / NF;
            int f = p - i * NF;
            float4 v4 = *(const float4*)&sV[i * 4];
            float4 x4 = *(const float4*)&sX[buf][f * 4];
            float4 u4;
            u4.x = v4.x * x4.x; u4.y = v4.y * x4.y;
            u4.z = v4.z * x4.z; u4.w = v4.w * x4.w;
            *(float4*)&sU[p * 4] = u4;
        }

        // ---- prefetch X(t+1) (hidden under the compute loop) ----
        if (t + 1 < TLEN && tid < NF * NB) {
            int b = tid & 3, f = tid >> 2;
            const float* src = x + ((size_t)(b0 + b) * TLEN + (t + 1)) * NF + f;
            cp_async4(xs_base + (uint32_t)((((t + 1) & 1) * NF * 4 + f * 4 + b) * 4), src);
        }
        cp_async_commit();
        __syncthreads();   // B1: U visible to everyone

        // ---- main GEMM-like loop: acc[b][j0..3] over this thread's i-subset ----
        float4 acc0 = make_float4(0.f, 0.f, 0.f, 0.f);
        float4 acc1 = make_float4(0.f, 0.f, 0.f, 0.f);
        float4 acc2 = make_float4(0.f, 0.f, 0.f, 0.f);
        float4 acc3 = make_float4(0.f, 0.f, 0.f, 0.f);

        #pragma unroll
        for (int ib = 0; ib < BOND; ib += 16) {
            const int i = ib + g;
            const float4* Up  = (const float4*)&sU[(i * NF) * 4];
            const float*  cp0 = core + (size_t)(i * NF) * BOND + jv * 4;
            #pragma unroll 11
            for (int f = 0; f < NF; ++f) {
                float4 u4 = Up[f];                                   // LDS.128 (bcast)
                float4 c4 = __ldg((const float4*)(cp0 + f * BOND));  // LDG.128 (L2 hit)
                acc0.x = fmaf(u4.x, c4.x, acc0.x); acc0.y = fmaf(u4.x, c4.y, acc0.y);
                acc0.z = fmaf(u4.x, c4.z, acc0.z); acc0.w = fmaf(u4.x, c4.w, acc0.w);
                acc1.x = fmaf(u4.y, c4.x, acc1.x); acc1.y = fmaf(u4.y, c4.y, acc1.y);
                acc1.z = fmaf(u4.y, c4.z, acc1.z); acc1.w = fmaf(u4.y, c4.w, acc1.w);
                acc2.x = fmaf(u4.z, c4.x, acc2.x); acc2.y = fmaf(u4.z, c4.y, acc2.y);
                acc2.z = fmaf(u4.z, c4.z, acc2.z); acc2.w = fmaf(u4.z, c4.w, acc2.w);
                acc3.x = fmaf(u4.w, c4.x, acc3.x); acc3.y = fmaf(u4.w, c4.y, acc3.y);
                acc3.z = fmaf(u4.w, c4.z, acc3.z); acc3.w = fmaf(u4.w, c4.w, acc3.w);
            }
        }

        __syncthreads();   // B2: all U reads done; sU reusable as partials

        // ---- store partials: P[(g*16+jv)*4 + b] as float4 ----
        {
            float* P = sU;
            int base = ((g * 16 + jv) * 4) * 4;
            *(float4*)&P[base + 0]  = acc0;
            *(float4*)&P[base + 4]  = acc1;
            *(float4*)&P[base + 8]  = acc2;
            *(float4*)&P[base + 12] = acc3;
        }
        __syncthreads();   // B3: partials visible

        // ---- reduce 16 i-groups -> V_new[j][b] ----
        {
            const float* P = sU;
            int b = tid >> 6;            // 0..3
            int j = tid & 63;            // 0..63
            int jv2 = j >> 2, jc = j & 3;
            float s = 0.f;
            #pragma unroll
            for (int gg = 0; gg < 16; ++gg)
                s += P[((gg * 16 + jv2) * 4 + b) * 4 + jc];
            sV[j * 4 + b] = s;           // j becomes next step's i
        }
        // visibility of sV handled by loop-top __syncthreads (B0)
    }

    __syncthreads();

    // ---- output: out[b][o] = sum_i V[i][b] * outc[i][o] ----
    if (tid < NB * OUTD) {
        int b = tid >> 5;    // 0..3
        int o = tid & 31;    // 0..31
        float s = 0.f;
        #pragma unroll 8
        for (int i = 0; i < BOND; ++i)
            s = fmaf(sV[i * 4 + b], __ldg(outc + i * OUTD + o), s);
        out[(size_t)(b0 + b) * OUTD + o] = s;
    }
}

extern "C" void kernel_launch(void* const* d_in, const int* in_sizes, int n_in,
                              void* d_out, int out_size) {
    const float* x     = (const float*)d_in[0];   // (256,512,33) fp32
    const float* core  = (const float*)d_in[1];   // (64,33,64)  fp32
    const float* alpha = (const float*)d_in[2];   // (64)        fp32
    const float* outc  = (const float*)d_in[3];   // (64,32)     fp32
    float* out = (float*)d_out;                   // (256,32)    fp32

    umps_chain_kernel<<<256 / NB, NTH>>>(x, core, alpha, outc, out);
}

// round 8
// speedup vs baseline: 1.5421x; 1.5421x over previous
#include <cuda_runtime.h>
#include <cstdint>

#define NF    33        // feature_dim + flag
#define BOND  64
#define NBC   8         // batches per cluster
#define CLU   4         // CTAs per cluster
#define ISL   16        // i-rows of core per CTA (BOND / CLU)
#define TLEN  512
#define NTH   256
#define OUTD  32

typedef unsigned long long u64;

// ---- shared memory layout (bytes) ----
#define CORE_OFF 0
#define CORE_SZ  (ISL * NF * BOND * 4)        // 135168
#define U_OFF    (CORE_OFF + CORE_SZ)
#define U_SZ     (ISL * NF * NBC * 4)         // 16896  (stored as 2112 u64 b-pairs)
#define P_OFF    (U_OFF + U_SZ)
#define P_SZ     (16 * 273 * 8)               // 34944  (padded partial buffer)
#define V_OFF    (P_OFF + P_SZ)
#define V_SZ     (BOND * NBC * 4)             // 2048
#define MAIL_OFF (V_OFF + V_SZ)
#define MAIL_SZ  (2 * 4 * 256 * 8)            // 16384  (double-buffered mailboxes)
#define X_OFF    (MAIL_OFF + MAIL_SZ)
#define X_SZ     (2 * NF * NBC * 4)           // 2112
#define SMEM_TOTAL (X_OFF + X_SZ)             // 207552

// ---- f32x2 packed math helpers ----
__device__ __forceinline__ u64 pack2(float v) {
    u64 r; asm("mov.b64 %0, {%1, %1};" : "=l"(r) : "f"(v)); return r;
}
__device__ __forceinline__ void fma2(u64& d, u64 a, u64 b) {
    asm("fma.rn.f32x2 %0, %1, %2, %0;" : "+l"(d) : "l"(a), "l"(b));
}
__device__ __forceinline__ u64 mul2(u64 a, u64 b) {
    u64 r; asm("mul.rn.f32x2 %0, %1, %2;" : "=l"(r) : "l"(a), "l"(b)); return r;
}
__device__ __forceinline__ void add2(u64& d, u64 a) {
    asm("add.rn.f32x2 %0, %0, %1;" : "+l"(d) : "l"(a));
}

__device__ __forceinline__ void cp_async4(uint32_t smem_addr, const void* gptr) {
    asm volatile("cp.async.ca.shared.global [%0], [%1], 4;\n" :: "r"(smem_addr), "l"(gptr));
}
__device__ __forceinline__ void cp_async_commit() {
    asm volatile("cp.async.commit_group;\n" ::: "memory");
}
__device__ __forceinline__ void cp_async_wait0() {
    asm volatile("cp.async.wait_group 0;\n" ::: "memory");
}

__device__ __forceinline__ void st_cluster_u64(uint32_t laddr, int dst_rank, u64 v) {
    uint32_t raddr;
    asm volatile("mapa.shared::cluster.u32 %0, %1, %2;" : "=r"(raddr) : "r"(laddr), "r"(dst_rank));
    asm volatile("st.shared::cluster.b64 [%0], %1;" :: "r"(raddr), "l"(v) : "memory");
}
__device__ __forceinline__ void cluster_barrier() {
    asm volatile("barrier.cluster.arrive.aligned;" ::: "memory");
    asm volatile("barrier.cluster.wait.aligned;" ::: "memory");
}

__global__ __launch_bounds__(NTH, 1) __cluster_dims__(CLU, 1, 1)
void umps_cluster_kernel(const float* __restrict__ x,      // (256, 512, 33)
                         const float* __restrict__ core,   // (64, 33, 64)
                         const float* __restrict__ alpha,  // (64)
                         const float* __restrict__ outc,   // (64, 32)
                         float*       __restrict__ out)    // (256, 32)
{
    extern __shared__ char smem[];
    float* sCore = (float*)(smem + CORE_OFF);   // [16 i_local][33 f][64 j]
    u64*   sU    = (u64*)  (smem + U_OFF);      // [(i_local*33+f)*4 + bp] b-pairs
    u64*   sP    = (u64*)  (smem + P_OFF);      // [jv][pad 273] inner=(jj*4+bp)*17+g
    float* sV    = (float*)(smem + V_OFF);      // [64 GLOBAL i][8 b]
    u64*   sMail = (u64*)  (smem + MAIL_OFF);   // [2 buf][4 rank][256]
    float* sX    = (float*)(smem + X_OFF);      // [2 buf][33 f][8 b]

    const int tid  = threadIdx.x;
    const int rank = blockIdx.x & 3;
    const int b0   = (blockIdx.x >> 2) * NBC;   // cluster's batch base
    const int g    = tid >> 4;                  // i_local 0..15
    const int jv   = tid & 15;                  // j = jv*4 .. +3
    const uint32_t smem_u32 = (uint32_t)__cvta_generic_to_shared(smem);

    // sV rows matching THIS CTA's core slice (global i = rank*ISL + i_local)
    const float* sVslice = sV + rank * ISL * NBC;

    // ---- load this rank's core slice into SMEM (once) ----
    {
        const float4* src = (const float4*)(core + (size_t)(rank * ISL) * NF * BOND);
        float4* dst = (float4*)sCore;
        for (int p = tid; p < ISL * NF * BOND / 4; p += NTH) dst[p] = src[p];
    }

    // ---- init V[i][b] = alpha[i]  (full 64-row V, replicated per CTA) ----
    for (int p = tid; p < BOND * NBC; p += NTH) sV[p] = alpha[p >> 3];

    // ---- preload X(t=0) ----
    for (int p = tid; p < NF * NBC; p += NTH) {
        int f = p >> 3, bl = p & 7;
        cp_async4(smem_u32 + X_OFF + (uint32_t)(p * 4),
                  x + ((size_t)(b0 + bl) * TLEN + 0) * NF + f);
    }
    cp_async_commit();

    for (int t = 0; t < TLEN; ++t) {
        cp_async_wait0();
        __syncthreads();                          // B0: X(t) landed, sV(t) visible

        // ---- build U b-pairs: U[i_local][f][bp] = V[rank*ISL+i_local][bp] * X[f][bp] ----
        const int buf = t & 1;
        const u64* sXu = (const u64*)(sX + buf * (NF * NBC));
        for (int p = tid; p < ISL * NF * 4; p += NTH) {   // 2112 entries
            int i = p / 132, r2 = p - i * 132;            // i = LOCAL row
            int f = r2 >> 2, bp = r2 & 3;
            u64 vv = *(const u64*)&sVslice[i * NBC + bp * 2];  // global-row V
            u64 xx = sXu[f * 4 + bp];
            sU[p] = mul2(vv, xx);
        }

        // ---- prefetch X(t+1) ----
        if (t + 1 < TLEN) {
            for (int p = tid; p < NF * NBC; p += NTH) {
                int f = p >> 3, bl = p & 7;
                cp_async4(smem_u32 + X_OFF + (uint32_t)((((t + 1) & 1) * NF * NBC + p) * 4),
                          x + ((size_t)(b0 + bl) * TLEN + (t + 1)) * NF + f);
            }
        }
        cp_async_commit();
        __syncthreads();                          // B1: U visible

        // ---- packed GEMM: acc[jj][bp] over this thread's core row i_local = g ----
        u64 acc[16];
        #pragma unroll
        for (int q = 0; q < 16; ++q) acc[q] = 0ull;

        const float4*     Crow = (const float4*)(sCore + g * (NF * BOND) + jv * 4);
        const ulonglong2* Urow = (const ulonglong2*)(sU + g * (NF * 4));

        #pragma unroll 11
        for (int f = 0; f < NF; ++f) {
            float4     c4 = Crow[f * 16];
            ulonglong2 ua = Urow[2 * f];
            ulonglong2 ub = Urow[2 * f + 1];
            u64 u0 = ua.x, u1 = ua.y, u2 = ub.x, u3 = ub.y;
            u64 cc;
            cc = pack2(c4.x);
            fma2(acc[0],  u0, cc); fma2(acc[1],  u1, cc);
            fma2(acc[2],  u2, cc); fma2(acc[3],  u3, cc);
            cc = pack2(c4.y);
            fma2(acc[4],  u0, cc); fma2(acc[5],  u1, cc);
            fma2(acc[6],  u2, cc); fma2(acc[7],  u3, cc);
            cc = pack2(c4.z);
            fma2(acc[8],  u0, cc); fma2(acc[9],  u1, cc);
            fma2(acc[10], u2, cc); fma2(acc[11], u3, cc);
            cc = pack2(c4.w);
            fma2(acc[12], u0, cc); fma2(acc[13], u1, cc);
            fma2(acc[14], u2, cc); fma2(acc[15], u3, cc);
        }

        // ---- store partials (padded layout, <=2-way conflicts) ----
        #pragma unroll
        for (int jj = 0; jj < 4; ++jj)
            #pragma unroll
            for (int bp = 0; bp < 4; ++bp)
                sP[jv * 273 + (jj * 4 + bp) * 17 + g] = acc[jj * 4 + bp];
        __syncthreads();                          // B2: partials visible

        // ---- local reduce over 16 i-rows -> this CTA's partial V ----
        const int j = tid >> 2, bp = tid & 3;
        {
            int base = (j >> 2) * 273 + ((j & 3) * 4 + bp) * 17;
            u64 s = sP[base];
            #pragma unroll
            for (int gg = 1; gg < 16; ++gg) add2(s, sP[base + gg]);

            // ---- push partial to all 4 CTAs' mailboxes (buffer t&1) ----
            uint32_t laddr = smem_u32 + MAIL_OFF +
                             (uint32_t)(((buf * 4 + rank) * 256 + tid) * 8);
            st_cluster_u64(laddr, 0, s);
            st_cluster_u64(laddr, 1, s);
            st_cluster_u64(laddr, 2, s);
            st_cluster_u64(laddr, 3, s);
        }

        cluster_barrier();                        // release/acquire: DSMEM writes ordered

        // ---- sum 4 rank-partials -> new full V (replicated) ----
        {
            const u64* mb = sMail + buf * 1024;
            u64 v = mb[tid];
            add2(v, mb[256 + tid]);
            add2(v, mb[512 + tid]);
            add2(v, mb[768 + tid]);
            *(u64*)&sV[j * NBC + bp * 2] = v;     // j becomes next step's global i
        }
        // sV visibility handled by loop-top B0
    }

    __syncthreads();

    // ---- epilogue: out[b][o] = sum_i V[i][b] * outc[i][o]  (rank 0 only) ----
    if (rank == 0) {
        int b = tid >> 5, o = tid & 31;
        float s = 0.f;
        #pragma unroll 8
        for (int i = 0; i < BOND; ++i)
            s = fmaf(sV[i * NBC + b], __ldg(outc + i * OUTD + o), s);
        out[(size_t)(b0 + b) * OUTD + o] = s;
    }
}

extern "C" void kernel_launch(void* const* d_in, const int* in_sizes, int n_in,
                              void* d_out, int out_size) {
    const float* x     = (const float*)d_in[0];   // (256,512,33) fp32
    const float* core  = (const float*)d_in[1];   // (64,33,64)  fp32
    const float* alpha = (const float*)d_in[2];   // (64)        fp32
    const float* outc  = (const float*)d_in[3];   // (64,32)     fp32
    float* out = (float*)d_out;                   // (256,32)    fp32

    cudaFuncSetAttribute(umps_cluster_kernel,
                         cudaFuncAttributeMaxDynamicSharedMemorySize, SMEM_TOTAL);
    // 32 clusters x 4 CTAs = 128 CTAs (one wave; cluster-4 cap is 132 SMs)
    umps_cluster_kernel<<<128, NTH, SMEM_TOTAL>>>(x, core, alpha, outc, out);
}

// round 9
// speedup vs baseline: 2.4645x; 1.5982x over previous
#include <cuda_runtime.h>
#include <cstdint>

#define NF    33        // feature_dim + flag
#define BOND  64
#define NBC   8         // batches per cluster
#define CLU   4         // CTAs per cluster
#define ISL   16        // i-rows of core per CTA (BOND / CLU)
#define TLEN  512
#define NTH   256
#define OUTD  32

typedef unsigned long long u64;

// ---- shared memory layout (bytes) ----
#define CORE_OFF 0
#define CORE_SZ  (ISL * NF * BOND * 4)        // 135168
#define U_OFF    (CORE_OFF + CORE_SZ)
#define U_SZ     (ISL * NF * NBC * 4)         // 16896  (stored as 2112 u64 b-pairs)
#define P_OFF    (U_OFF + U_SZ)
#define P_SZ     (16 * 273 * 8)               // 34944  (padded partial buffer)
#define V_OFF    (P_OFF + P_SZ)
#define V_SZ     (BOND * NBC * 4)             // 2048
#define MAIL_OFF (V_OFF + V_SZ)
#define MAIL_SZ  (2 * 4 * 256 * 8)            // 16384  (double-buffered mailboxes)
#define X_OFF    (MAIL_OFF + MAIL_SZ)
#define X_SZ     (2 * NF * NBC * 4)           // 2112
#define SMEM_TOTAL (X_OFF + X_SZ)             // 207552

// ---- f32x2 packed math helpers ----
__device__ __forceinline__ u64 pack2(float v) {
    u64 r; asm("mov.b64 %0, {%1, %1};" : "=l"(r) : "f"(v)); return r;
}
__device__ __forceinline__ void fma2(u64& d, u64 a, u64 b) {
    asm("fma.rn.f32x2 %0, %1, %2, %0;" : "+l"(d) : "l"(a), "l"(b));
}
__device__ __forceinline__ u64 mul2(u64 a, u64 b) {
    u64 r; asm("mul.rn.f32x2 %0, %1, %2;" : "=l"(r) : "l"(a), "l"(b)); return r;
}
__device__ __forceinline__ void add2(u64& d, u64 a) {
    asm("add.rn.f32x2 %0, %0, %1;" : "+l"(d) : "l"(a));
}

__device__ __forceinline__ void cp_async4(uint32_t smem_addr, const void* gptr) {
    asm volatile("cp.async.ca.shared.global [%0], [%1], 4;\n" :: "r"(smem_addr), "l"(gptr));
}
__device__ __forceinline__ void cp_async_commit() {
    asm volatile("cp.async.commit_group;\n" ::: "memory");
}
__device__ __forceinline__ void cp_async_wait0() {
    asm volatile("cp.async.wait_group 0;\n" ::: "memory");
}

__device__ __forceinline__ void st_cluster_u64(uint32_t laddr, int dst_rank, u64 v) {
    uint32_t raddr;
    asm volatile("mapa.shared::cluster.u32 %0, %1, %2;" : "=r"(raddr) : "r"(laddr), "r"(dst_rank));
    asm volatile("st.shared::cluster.b64 [%0], %1;" :: "r"(raddr), "l"(v) : "memory");
}
__device__ __forceinline__ void cluster_barrier() {
    asm volatile("barrier.cluster.arrive.aligned;" ::: "memory");
    asm volatile("barrier.cluster.wait.aligned;" ::: "memory");
}

__global__ __launch_bounds__(NTH, 1) __cluster_dims__(CLU, 1, 1)
void umps_cluster_kernel(const float* __restrict__ x,      // (256, 512, 33)
                         const float* __restrict__ core,   // (64, 33, 64)
                         const float* __restrict__ alpha,  // (64)
                         const float* __restrict__ outc,   // (64, 32)
                         float*       __restrict__ out)    // (256, 32)
{
    extern __shared__ char smem[];
    float* sCore = (float*)(smem + CORE_OFF);   // [16 i_local][33 f][64 j]
    u64*   sU    = (u64*)  (smem + U_OFF);      // [(i_local*33+f)*4 + bp] b-pairs
    u64*   sP    = (u64*)  (smem + P_OFF);      // [jv][pad 273] inner=(jj*4+bp)*17+g
    float* sV    = (float*)(smem + V_OFF);      // [64 GLOBAL i][8 b]
    u64*   sMail = (u64*)  (smem + MAIL_OFF);   // [2 buf][4 rank][256]
    float* sX    = (float*)(smem + X_OFF);      // [2 buf][33 f][8 b]

    const int tid  = threadIdx.x;
    const int rank = blockIdx.x & 3;
    const int b0   = (blockIdx.x >> 2) * NBC;   // cluster's batch base
    const int g    = tid >> 4;                  // i_local 0..15
    const int jv   = tid & 15;                  // j = jv*4 .. +3
    const uint32_t smem_u32 = (uint32_t)__cvta_generic_to_shared(smem);

    // sV rows matching THIS CTA's core slice (global i = rank*ISL + i_local)
    const float* sVslice = sV + rank * ISL * NBC;

    // ---- load this rank's core slice into SMEM (once) ----
    {
        const float4* src = (const float4*)(core + (size_t)(rank * ISL) * NF * BOND);
        float4* dst = (float4*)sCore;
        for (int p = tid; p < ISL * NF * BOND / 4; p += NTH) dst[p] = src[p];
    }

    // ---- init V[i][b] = alpha[i]  (full 64-row V, replicated per CTA) ----
    for (int p = tid; p < BOND * NBC; p += NTH) sV[p] = alpha[p >> 3];

    // ---- preload X(t=0) ----
    for (int p = tid; p < NF * NBC; p += NTH) {
        int f = p >> 3, bl = p & 7;
        cp_async4(smem_u32 + X_OFF + (uint32_t)(p * 4),
                  x + ((size_t)(b0 + bl) * TLEN + 0) * NF + f);
    }
    cp_async_commit();

    for (int t = 0; t < TLEN; ++t) {
        cp_async_wait0();
        __syncthreads();                          // B0: X(t) landed, sV(t) visible

        // ---- build U b-pairs: U[i_local][f][bp] = V[rank*ISL+i_local][bp] * X[f][bp] ----
        const int buf = t & 1;
        const u64* sXu = (const u64*)(sX + buf * (NF * NBC));
        for (int p = tid; p < ISL * NF * 4; p += NTH) {   // 2112 entries
            int i = p / 132, r2 = p - i * 132;            // i = LOCAL row
            int f = r2 >> 2, bp = r2 & 3;
            u64 vv = *(const u64*)&sVslice[i * NBC + bp * 2];  // global-row V
            u64 xx = sXu[f * 4 + bp];
            sU[p] = mul2(vv, xx);
        }

        // ---- prefetch X(t+1) ----
        if (t + 1 < TLEN) {
            for (int p = tid; p < NF * NBC; p += NTH) {
                int f = p >> 3, bl = p & 7;
                cp_async4(smem_u32 + X_OFF + (uint32_t)((((t + 1) & 1) * NF * NBC + p) * 4),
                          x + ((size_t)(b0 + bl) * TLEN + (t + 1)) * NF + f);
            }
        }
        cp_async_commit();
        __syncthreads();                          // B1: U visible

        // ---- packed GEMM: acc[jj][bp] over this thread's core row i_local = g ----
        u64 acc[16];
        #pragma unroll
        for (int q = 0; q < 16; ++q) acc[q] = 0ull;

        const float4*     Crow = (const float4*)(sCore + g * (NF * BOND) + jv * 4);
        const ulonglong2* Urow = (const ulonglong2*)(sU + g * (NF * 4));

        #pragma unroll 11
        for (int f = 0; f < NF; ++f) {
            float4     c4 = Crow[f * 16];
            ulonglong2 ua = Urow[2 * f];
            ulonglong2 ub = Urow[2 * f + 1];
            u64 u0 = ua.x, u1 = ua.y, u2 = ub.x, u3 = ub.y;
            u64 cc;
            cc = pack2(c4.x);
            fma2(acc[0],  u0, cc); fma2(acc[1],  u1, cc);
            fma2(acc[2],  u2, cc); fma2(acc[3],  u3, cc);
            cc = pack2(c4.y);
            fma2(acc[4],  u0, cc); fma2(acc[5],  u1, cc);
            fma2(acc[6],  u2, cc); fma2(acc[7],  u3, cc);
            cc = pack2(c4.z);
            fma2(acc[8],  u0, cc); fma2(acc[9],  u1, cc);
            fma2(acc[10], u2, cc); fma2(acc[11], u3, cc);
            cc = pack2(c4.w);
            fma2(acc[12], u0, cc); fma2(acc[13], u1, cc);
            fma2(acc[14], u2, cc); fma2(acc[15], u3, cc);
        }

        // ---- store partials (padded layout, <=2-way conflicts) ----
        #pragma unroll
        for (int jj = 0; jj < 4; ++jj)
            #pragma unroll
            for (int bp = 0; bp < 4; ++bp)
                sP[jv * 273 + (jj * 4 + bp) * 17 + g] = acc[jj * 4 + bp];
        __syncthreads();                          // B2: partials visible

        // ---- local reduce over 16 i-rows -> this CTA's partial V ----
        const int j = tid >> 2, bp = tid & 3;
        {
            int base = (j >> 2) * 273 + ((j & 3) * 4 + bp) * 17;
            u64 s = sP[base];
            #pragma unroll
            for (int gg = 1; gg < 16; ++gg) add2(s, sP[base + gg]);

            // ---- push partial to all 4 CTAs' mailboxes (buffer t&1) ----
            uint32_t laddr = smem_u32 + MAIL_OFF +
                             (uint32_t)(((buf * 4 + rank) * 256 + tid) * 8);
            st_cluster_u64(laddr, 0, s);
            st_cluster_u64(laddr, 1, s);
            st_cluster_u64(laddr, 2, s);
            st_cluster_u64(laddr, 3, s);
        }

        cluster_barrier();                        // release/acquire: DSMEM writes ordered

        // ---- sum 4 rank-partials -> new full V (replicated) ----
        {
            const u64* mb = sMail + buf * 1024;
            u64 v = mb[tid];
            add2(v, mb[256 + tid]);
            add2(v, mb[512 + tid]);
            add2(v, mb[768 + tid]);
            *(u64*)&sV[j * NBC + bp * 2] = v;     // j becomes next step's global i
        }
        // sV visibility handled by loop-top B0
    }

    __syncthreads();

    // ---- epilogue: out[b][o] = sum_i V[i][b] * outc[i][o]  (rank 0 only) ----
    if (rank == 0) {
        int b = tid >> 5, o = tid & 31;
        float s = 0.f;
        #pragma unroll 8
        for (int i = 0; i < BOND; ++i)
            s = fmaf(sV[i * NBC + b], __ldg(outc + i * OUTD + o), s);
        out[(size_t)(b0 + b) * OUTD + o] = s;
    }
}

extern "C" void kernel_launch(void* const* d_in, const int* in_sizes, int n_in,
                              void* d_out, int out_size) {
    const float* x     = (const float*)d_in[0];   // (256,512,33) fp32
    const float* core  = (const float*)d_in[1];   // (64,33,64)  fp32
    const float* alpha = (const float*)d_in[2];   // (64)        fp32
    const float* outc  = (const float*)d_in[3];   // (64,32)     fp32
    float* out = (float*)d_out;                   // (256,32)    fp32

    cudaFuncSetAttribute(umps_cluster_kernel,
                         cudaFuncAttributeMaxDynamicSharedMemorySize, SMEM_TOTAL);
    // 32 clusters x 4 CTAs = 128 CTAs (one wave; cluster-4 cap is 132 SMs)
    umps_cluster_kernel<<<128, NTH, SMEM_TOTAL>>>(x, core, alpha, outc, out);
}